// round 1
// baseline (speedup 1.0000x reference)
#include <cuda_runtime.h>
#include <cuda_bf16.h>

#define BATCH  16384
#define DIM    128
#define NEDGES 500000
#define EPSL   1e-6f

// ---------------- device scratch (allowed: static __device__ globals) ----------
__device__ float  g_ps[BATCH * DIM];   // p_star[nodes_p_star]  (rows of dist_mat)
__device__ float  g_pp[BATCH * DIM];   // p[nodes_p]            (cols of dist_mat)
__device__ float  g_ns[BATCH];         // ||ps_row||^2
__device__ float  g_nq[BATCH];         // ||pp_row||^2
__device__ float  g_bps[BATCH];        // beta_p_star[nodes_p_star]
__device__ float  g_bp[BATCH];         // beta_p[nodes_p]
__device__ double g_acc[2];            // [0] = link_term, [1] = non_link

// ---------------- zero accumulators --------------------------------------------
__global__ void zero_kernel() {
    if (threadIdx.x == 0) { g_acc[0] = 0.0; g_acc[1] = 0.0; }
}

// ---------------- gather rows + norms + betas -----------------------------------
// one warp per output row; warps [0,BATCH) -> ps, [BATCH,2*BATCH) -> pp
__global__ void gather_kernel(const int* __restrict__ nodes_p_star,
                              const int* __restrict__ nodes_p,
                              const float* __restrict__ beta_p,
                              const float* __restrict__ beta_p_star,
                              const float* __restrict__ p,
                              const float* __restrict__ p_star) {
    int gw   = (blockIdx.x * blockDim.x + threadIdx.x) >> 5;
    int lane = threadIdx.x & 31;
    if (gw >= 2 * BATCH) return;
    bool is_ps = (gw < BATCH);
    int r   = is_ps ? gw : gw - BATCH;
    int idx = is_ps ? nodes_p_star[r] : nodes_p[r];
    const float4* src = (const float4*)((is_ps ? p_star : p) + (size_t)idx * DIM);
    float4*       dst = (float4*)((is_ps ? g_ps : g_pp) + (size_t)r * DIM);
    float nrm = 0.f;
#pragma unroll
    for (int c = lane; c < DIM / 4; c += 32) {
        float4 v = src[c];
        dst[c] = v;
        nrm += v.x * v.x + v.y * v.y + v.z * v.z + v.w * v.w;
    }
#pragma unroll
    for (int o = 16; o; o >>= 1) nrm += __shfl_xor_sync(0xffffffffu, nrm, o);
    if (lane == 0) {
        if (is_ps) { g_ns[r] = nrm; g_bps[r] = beta_p_star[idx]; }
        else       { g_nq[r] = nrm; g_bp[r]  = beta_p[idx]; }
    }
}

// ---------------- link term: one warp per edge ----------------------------------
__global__ void link_kernel(const int* __restrict__ edges,
                            const float* __restrict__ beta_p,
                            const float* __restrict__ beta_p_star,
                            const float* __restrict__ p,
                            const float* __restrict__ p_star) {
    int gw   = (blockIdx.x * blockDim.x + threadIdx.x) >> 5;
    int lane = threadIdx.x & 31;
    int wid  = threadIdx.x >> 5;
    float contrib = 0.f;
    if (gw < NEDGES) {
        int i0 = edges[gw];
        int i1 = edges[NEDGES + gw];
        const float4* a = (const float4*)(p      + (size_t)i0 * DIM);
        const float4* b = (const float4*)(p_star + (size_t)i1 * DIM);
        float4 av = a[lane];
        float4 bv = b[lane];
        float dx = av.x - bv.x + EPSL;
        float dy = av.y - bv.y + EPSL;
        float dz = av.z - bv.z + EPSL;
        float dw = av.w - bv.w + EPSL;
        float s = dx * dx + dy * dy + dz * dz + dw * dw;
#pragma unroll
        for (int o = 16; o; o >>= 1) s += __shfl_xor_sync(0xffffffffu, s, o);
        if (lane == 0)
            contrib = beta_p_star[i0] + beta_p[i1] - sqrtf(s);
    }
    __shared__ double red[8];
    if (lane == 0) red[wid] = (double)contrib;
    __syncthreads();
    if (threadIdx.x == 0) {
        double t = 0.0;
#pragma unroll
        for (int w = 0; w < 8; w++) t += red[w];
        atomicAdd(&g_acc[0], t);
    }
}

// ---------------- non-link term: 128x128 tile, fused epilogue -------------------
// grid (128,128): blockIdx.y = s-tile, blockIdx.x = q-tile; need q > s -> tq >= ts
__global__ void __launch_bounds__(256) nonlink_kernel() {
    int ts = blockIdx.y, tq = blockIdx.x;
    if (tq < ts) return;

    extern __shared__ float sm[];
    float* As = sm;               // As[k][s] : DIM x 128 (transposed on load)
    float* Bs = sm + DIM * 128;   // Bs[k][q] : DIM x 128

    int tid = threadIdx.x;
    int s0 = ts * 128, q0 = tq * 128;

    // cooperative load + transpose: thread -> (row = tid&127, c4 start = tid>>7)
    {
        int row = tid & 127;
        int c0  = tid >> 7; // 0 or 1
        const float4* srcA = (const float4*)(g_ps + (size_t)(s0 + row) * DIM);
        const float4* srcB = (const float4*)(g_pp + (size_t)(q0 + row) * DIM);
#pragma unroll
        for (int c4 = c0; c4 < DIM / 4; c4 += 2) {
            float4 v = srcA[c4];
            As[(4 * c4 + 0) * 128 + row] = v.x;
            As[(4 * c4 + 1) * 128 + row] = v.y;
            As[(4 * c4 + 2) * 128 + row] = v.z;
            As[(4 * c4 + 3) * 128 + row] = v.w;
            float4 w = srcB[c4];
            Bs[(4 * c4 + 0) * 128 + row] = w.x;
            Bs[(4 * c4 + 1) * 128 + row] = w.y;
            Bs[(4 * c4 + 2) * 128 + row] = w.z;
            Bs[(4 * c4 + 3) * 128 + row] = w.w;
        }
    }
    __syncthreads();

    int tx = tid & 15;   // q micro-tile
    int ty = tid >> 4;   // s micro-tile
    float acc[8][8];
#pragma unroll
    for (int i = 0; i < 8; i++)
#pragma unroll
        for (int j = 0; j < 8; j++) acc[i][j] = 0.f;

#pragma unroll 4
    for (int k = 0; k < DIM; k++) {
        float a[8], b[8];
        float4 a0 = *(const float4*)&As[k * 128 + ty * 8];
        float4 a1 = *(const float4*)&As[k * 128 + ty * 8 + 4];
        float4 b0 = *(const float4*)&Bs[k * 128 + tx * 8];
        float4 b1 = *(const float4*)&Bs[k * 128 + tx * 8 + 4];
        a[0] = a0.x; a[1] = a0.y; a[2] = a0.z; a[3] = a0.w;
        a[4] = a1.x; a[5] = a1.y; a[6] = a1.z; a[7] = a1.w;
        b[0] = b0.x; b[1] = b0.y; b[2] = b0.z; b[3] = b0.w;
        b[4] = b1.x; b[5] = b1.y; b[6] = b1.z; b[7] = b1.w;
#pragma unroll
        for (int i = 0; i < 8; i++)
#pragma unroll
            for (int j = 0; j < 8; j++)
                acc[i][j] = fmaf(a[i], b[j], acc[i][j]);
    }

    // fused epilogue
    int sbase = s0 + ty * 8;
    int qbase = q0 + tx * 8;
    float ns_i[8], bps_i[8], nq_j[8], bp_j[8];
#pragma unroll
    for (int i = 0; i < 8; i++) { ns_i[i] = g_ns[sbase + i]; bps_i[i] = g_bps[sbase + i]; }
#pragma unroll
    for (int j = 0; j < 8; j++) { nq_j[j] = g_nq[qbase + j]; bp_j[j] = g_bp[qbase + j]; }

    bool diag = (ts == tq);
    float lsum = 0.f;
#pragma unroll
    for (int i = 0; i < 8; i++) {
#pragma unroll
        for (int j = 0; j < 8; j++) {
            float sq = ns_i[i] + nq_j[j] - 2.f * acc[i][j];
            sq = fmaxf(sq, 0.f);
            float d = sqrtf(sq);
            float t = __expf(bps_i[i] + bp_j[j] - d);
            bool include = !diag || ((qbase + j) > (sbase + i));
            lsum += include ? t : 0.f;
        }
    }

    // block reduce -> double atomic
#pragma unroll
    for (int o = 16; o; o >>= 1) lsum += __shfl_xor_sync(0xffffffffu, lsum, o);
    __shared__ double red[8];
    int wid = tid >> 5, lane = tid & 31;
    if (lane == 0) red[wid] = (double)lsum;
    __syncthreads();
    if (tid == 0) {
        double t = 0.0;
#pragma unroll
        for (int w = 0; w < 8; w++) t += red[w];
        atomicAdd(&g_acc[1], t);
    }
}

// ---------------- finalize -------------------------------------------------------
__global__ void finalize_kernel(float* out) {
    if (threadIdx.x == 0)
        out[0] = (float)(g_acc[1] - g_acc[0]);  // -(link - nonlink)
}

// ---------------- launch ---------------------------------------------------------
extern "C" void kernel_launch(void* const* d_in, const int* in_sizes, int n_in,
                              void* d_out, int out_size) {
    const int*   edges        = (const int*)d_in[0];
    const int*   nodes_p_star = (const int*)d_in[1];
    const int*   nodes_p      = (const int*)d_in[2];
    const float* beta_p       = (const float*)d_in[3];
    const float* beta_p_star  = (const float*)d_in[4];
    const float* p            = (const float*)d_in[5];
    const float* p_star       = (const float*)d_in[6];
    float* out = (float*)d_out;

    static const size_t NL_SMEM = 2 * DIM * 128 * sizeof(float); // 128 KB
    cudaFuncSetAttribute(nonlink_kernel,
                         cudaFuncAttributeMaxDynamicSharedMemorySize, (int)NL_SMEM);

    zero_kernel<<<1, 32>>>();

    // gather: 2*BATCH warps, 8 warps/block
    gather_kernel<<<(2 * BATCH) / 8, 256>>>(nodes_p_star, nodes_p,
                                            beta_p, beta_p_star, p, p_star);

    // link: one warp per edge, 8 warps/block
    link_kernel<<<(NEDGES + 7) / 8, 256>>>(edges, beta_p, beta_p_star, p, p_star);

    // non-link: triangular 128x128 tiles
    dim3 grid(BATCH / 128, BATCH / 128);
    nonlink_kernel<<<grid, 256, NL_SMEM>>>();

    finalize_kernel<<<1, 32>>>(out);
}

// round 2
// speedup vs baseline: 3.7323x; 3.7323x over previous
#include <cuda_runtime.h>
#include <cuda_bf16.h>
#include <cstdint>

#define BATCH  16384
#define DIM    128
#define NEDGES 500000
#define EPSL   1e-6f
#define PITCH  136   // bf16 elems per smem row (272 B = 17*16B -> conflict-free)

// ---------------- device scratch ------------------------------------------------
__device__ float          g_ns[BATCH];          // ||ps_row||^2 (exact fp32)
__device__ float          g_nq[BATCH];          // ||pp_row||^2
__device__ float          g_bps[BATCH];         // beta_p_star[nodes_p_star]
__device__ float          g_bp[BATCH];          // beta_p[nodes_p]
__device__ __nv_bfloat16  g_psh[BATCH * DIM];   // bf16 gathered p_star rows
__device__ __nv_bfloat16  g_pph[BATCH * DIM];   // bf16 gathered p rows
__device__ double         g_acc[2];             // [0]=link, [1]=non_link

// ---------------- zero ----------------------------------------------------------
__global__ void zero_kernel() {
    if (threadIdx.x == 0) { g_acc[0] = 0.0; g_acc[1] = 0.0; }
}

// ---------------- gather: fp32 norms/betas + bf16 row copies --------------------
__global__ void gather_kernel(const int* __restrict__ nodes_p_star,
                              const int* __restrict__ nodes_p,
                              const float* __restrict__ beta_p,
                              const float* __restrict__ beta_p_star,
                              const float* __restrict__ p,
                              const float* __restrict__ p_star) {
    int gw   = (blockIdx.x * blockDim.x + threadIdx.x) >> 5;
    int lane = threadIdx.x & 31;
    if (gw >= 2 * BATCH) return;
    bool is_ps = (gw < BATCH);
    int r   = is_ps ? gw : gw - BATCH;
    int idx = is_ps ? nodes_p_star[r] : nodes_p[r];
    const float4* src = (const float4*)((is_ps ? p_star : p) + (size_t)idx * DIM);
    __nv_bfloat162* dsth = (__nv_bfloat162*)((is_ps ? g_psh : g_pph) + (size_t)r * DIM);
    float nrm = 0.f;
#pragma unroll
    for (int c = lane; c < DIM / 4; c += 32) {
        float4 v = src[c];
        nrm += v.x * v.x + v.y * v.y + v.z * v.z + v.w * v.w;
        dsth[2 * c]     = __floats2bfloat162_rn(v.x, v.y);
        dsth[2 * c + 1] = __floats2bfloat162_rn(v.z, v.w);
    }
#pragma unroll
    for (int o = 16; o; o >>= 1) nrm += __shfl_xor_sync(0xffffffffu, nrm, o);
    if (lane == 0) {
        if (is_ps) { g_ns[r] = nrm; g_bps[r] = beta_p_star[idx]; }
        else       { g_nq[r] = nrm; g_bp[r]  = beta_p[idx]; }
    }
}

// ---------------- link term: one warp per edge ----------------------------------
__global__ void link_kernel(const int* __restrict__ edges,
                            const float* __restrict__ beta_p,
                            const float* __restrict__ beta_p_star,
                            const float* __restrict__ p,
                            const float* __restrict__ p_star) {
    int gw   = (blockIdx.x * blockDim.x + threadIdx.x) >> 5;
    int lane = threadIdx.x & 31;
    int wid  = threadIdx.x >> 5;
    float contrib = 0.f;
    if (gw < NEDGES) {
        int i0 = edges[gw];
        int i1 = edges[NEDGES + gw];
        float4 av = ((const float4*)(p      + (size_t)i0 * DIM))[lane];
        float4 bv = ((const float4*)(p_star + (size_t)i1 * DIM))[lane];
        float dx = av.x - bv.x + EPSL;
        float dy = av.y - bv.y + EPSL;
        float dz = av.z - bv.z + EPSL;
        float dw = av.w - bv.w + EPSL;
        float s = dx * dx + dy * dy + dz * dz + dw * dw;
#pragma unroll
        for (int o = 16; o; o >>= 1) s += __shfl_xor_sync(0xffffffffu, s, o);
        if (lane == 0)
            contrib = beta_p_star[i0] + beta_p[i1] - sqrtf(s);
    }
    __shared__ double red[8];
    if (lane == 0) red[wid] = (double)contrib;
    __syncthreads();
    if (threadIdx.x == 0) {
        double t = 0.0;
#pragma unroll
        for (int w = 0; w < 8; w++) t += red[w];
        atomicAdd(&g_acc[0], t);
    }
}

// ---------------- MMA helpers ---------------------------------------------------
__device__ __forceinline__ void ldsm_x4(uint32_t& r0, uint32_t& r1,
                                        uint32_t& r2, uint32_t& r3, const void* p) {
    uint32_t a = (uint32_t)__cvta_generic_to_shared(p);
    asm volatile("ldmatrix.sync.aligned.m8n8.x4.shared.b16 {%0,%1,%2,%3},[%4];"
                 : "=r"(r0), "=r"(r1), "=r"(r2), "=r"(r3) : "r"(a));
}

__device__ __forceinline__ void mma16816(float* c, const uint32_t* a, const uint32_t* b) {
    asm volatile(
        "mma.sync.aligned.m16n8k16.row.col.f32.bf16.bf16.f32 "
        "{%0,%1,%2,%3},{%4,%5,%6,%7},{%8,%9},{%0,%1,%2,%3};"
        : "+f"(c[0]), "+f"(c[1]), "+f"(c[2]), "+f"(c[3])
        : "r"(a[0]), "r"(a[1]), "r"(a[2]), "r"(a[3]), "r"(b[0]), "r"(b[1]));
}

// ---------------- non-link: 128x128 bf16 tensor tile, fused epilogue ------------
// warp (of 8): wm = wid&1 -> 64 M rows, wn = wid>>1 -> 32 N cols
__global__ void __launch_bounds__(256, 2) nonlink_kernel() {
    int ts = blockIdx.y, tq = blockIdx.x;
    if (tq < ts) return;

    extern __shared__ __nv_bfloat16 sm[];
    __nv_bfloat16* As = sm;                 // [128][PITCH]
    __nv_bfloat16* Bs = sm + 128 * PITCH;   // [128][PITCH]

    int tid  = threadIdx.x;
    int lane = tid & 31;
    int wid  = tid >> 5;
    int s0 = ts * 128, q0 = tq * 128;

    // cooperative load: thread -> chunk (tid&15, 8 bf16 = 16B), rows tid>>4 + 16*i
    {
        int chunk = tid & 15;
        int rbase = tid >> 4;
#pragma unroll
        for (int i = 0; i < 8; i++) {
            int row = rbase + 16 * i;
            uint4 va = ((const uint4*)(g_psh + (size_t)(s0 + row) * DIM))[chunk];
            uint4 vb = ((const uint4*)(g_pph + (size_t)(q0 + row) * DIM))[chunk];
            *(uint4*)(As + row * PITCH + chunk * 8) = va;
            *(uint4*)(Bs + row * PITCH + chunk * 8) = vb;
        }
    }
    __syncthreads();

    int wm = wid & 1;         // 0..1  -> M offset 64*wm
    int wn = wid >> 1;        // 0..3  -> N offset 32*wn
    int m_base = wm * 64;
    int n_base = wn * 32;

    float acc[4][4][4];
#pragma unroll
    for (int mi = 0; mi < 4; mi++)
#pragma unroll
        for (int nj = 0; nj < 4; nj++)
#pragma unroll
            for (int r = 0; r < 4; r++) acc[mi][nj][r] = 0.f;

    // ldmatrix lane addressing
    int a_row_off = lane & 15;          // + 8*(lane>>4) on k
    int a_k_off   = 8 * (lane >> 4);
    int b_row_off = ((lane >> 4) << 3) + (lane & 7);
    int b_k_off   = ((lane >> 3) & 1) * 8;

#pragma unroll
    for (int k0 = 0; k0 < DIM; k0 += 16) {
        uint32_t a[4][4];
#pragma unroll
        for (int mi = 0; mi < 4; mi++) {
            const __nv_bfloat16* pa =
                As + (m_base + mi * 16 + a_row_off) * PITCH + k0 + a_k_off;
            ldsm_x4(a[mi][0], a[mi][1], a[mi][2], a[mi][3], pa);
        }
        uint32_t b[4][2];
#pragma unroll
        for (int pr = 0; pr < 2; pr++) {
            const __nv_bfloat16* pb =
                Bs + (n_base + pr * 16 + b_row_off) * PITCH + k0 + b_k_off;
            uint32_t r0, r1, r2, r3;
            ldsm_x4(r0, r1, r2, r3, pb);
            b[pr * 2][0] = r0; b[pr * 2][1] = r1;
            b[pr * 2 + 1][0] = r2; b[pr * 2 + 1][1] = r3;
        }
#pragma unroll
        for (int mi = 0; mi < 4; mi++)
#pragma unroll
            for (int nj = 0; nj < 4; nj++)
                mma16816(acc[mi][nj], a[mi], b[nj]);
    }

    // ---------- fused epilogue ----------
    int g = lane >> 2, t = lane & 3;
    float nsv[8], bpsv[8];
#pragma unroll
    for (int mi = 0; mi < 4; mi++) {
        int r = s0 + m_base + mi * 16 + g;
        nsv[2 * mi]      = g_ns[r];      nsv[2 * mi + 1]  = g_ns[r + 8];
        bpsv[2 * mi]     = g_bps[r];     bpsv[2 * mi + 1] = g_bps[r + 8];
    }
    float nqv[8], bpv[8];
#pragma unroll
    for (int nj = 0; nj < 4; nj++) {
        int c = q0 + n_base + nj * 8 + 2 * t;
        nqv[2 * nj]      = g_nq[c];      nqv[2 * nj + 1] = g_nq[c + 1];
        bpv[2 * nj]      = g_bp[c];      bpv[2 * nj + 1] = g_bp[c + 1];
    }

    bool diag = (ts == tq);
    float lsum = 0.f;
#pragma unroll
    for (int mi = 0; mi < 4; mi++) {
        int r0g = s0 + m_base + mi * 16 + g;
#pragma unroll
        for (int nj = 0; nj < 4; nj++) {
            int c0g = q0 + n_base + nj * 8 + 2 * t;
#pragma unroll
            for (int rr = 0; rr < 4; rr++) {
                int rowg = r0g + (rr >> 1) * 8;          // rr 0,1 -> +0 ; 2,3 -> +8
                int colg = c0g + (rr & 1);               // rr even -> +0 ; odd -> +1
                float ns = nsv[2 * mi + (rr >> 1)];
                float bs = bpsv[2 * mi + (rr >> 1)];
                float nq = nqv[2 * nj + (rr & 1)];
                float bq = bpv[2 * nj + (rr & 1)];
                float sq = fmaxf(ns + nq - 2.f * acc[mi][nj][rr], 0.f);
                float d  = sqrtf(sq);
                float e  = __expf(bs + bq - d);
                bool include = !diag || (colg > rowg);
                lsum += include ? e : 0.f;
            }
        }
    }

#pragma unroll
    for (int o = 16; o; o >>= 1) lsum += __shfl_xor_sync(0xffffffffu, lsum, o);
    __shared__ double red[8];
    if (lane == 0) red[wid] = (double)lsum;
    __syncthreads();
    if (tid == 0) {
        double s = 0.0;
#pragma unroll
        for (int w = 0; w < 8; w++) s += red[w];
        atomicAdd(&g_acc[1], s);
    }
}

// ---------------- finalize ------------------------------------------------------
__global__ void finalize_kernel(float* out) {
    if (threadIdx.x == 0)
        out[0] = (float)(g_acc[1] - g_acc[0]);  // -(link - nonlink)
}

// ---------------- launch --------------------------------------------------------
extern "C" void kernel_launch(void* const* d_in, const int* in_sizes, int n_in,
                              void* d_out, int out_size) {
    const int*   edges        = (const int*)d_in[0];
    const int*   nodes_p_star = (const int*)d_in[1];
    const int*   nodes_p      = (const int*)d_in[2];
    const float* beta_p       = (const float*)d_in[3];
    const float* beta_p_star  = (const float*)d_in[4];
    const float* p            = (const float*)d_in[5];
    const float* p_star       = (const float*)d_in[6];
    float* out = (float*)d_out;

    static const size_t NL_SMEM = 2 * 128 * PITCH * sizeof(__nv_bfloat16); // 69632 B
    cudaFuncSetAttribute(nonlink_kernel,
                         cudaFuncAttributeMaxDynamicSharedMemorySize, (int)NL_SMEM);

    zero_kernel<<<1, 32>>>();

    gather_kernel<<<(2 * BATCH) / 8, 256>>>(nodes_p_star, nodes_p,
                                            beta_p, beta_p_star, p, p_star);

    link_kernel<<<(NEDGES + 7) / 8, 256>>>(edges, beta_p, beta_p_star, p, p_star);

    dim3 grid(BATCH / 128, BATCH / 128);
    nonlink_kernel<<<grid, 256, NL_SMEM>>>();

    finalize_kernel<<<1, 32>>>(out);
}